// round 2
// baseline (speedup 1.0000x reference)
#include <cuda_runtime.h>
#include <math.h>

#define NT     365
#define NGRID  2048
#define NX     16
#define NH     256
#define G4     1024              // 4*NH
#define K2     512               // combined k = NH (h) + NH (x0)
#define NROWS  (NT * NGRID)      // 747520

// ---------------- scratch (static __device__, no allocations) ----------------
// NOTE: total static size must stay well under 2 GB or the host link fails
// (GOTPCREL relocation overflow). x0 = 765 MB, weights ~3 MB. OK.
__device__ float g_x0[(size_t)NROWS * NH];            // ~765 MB
__device__ float g_wc[(K2 + 4) * G4];                 // combined [k][u][gate], +4 pad rows

__device__ __forceinline__ float sigf(float x) {
    return 1.0f / (1.0f + __expf(-x));
}

// ---------------- kernel 0: pack combined weights ----------------
// act vector layout: k in [0,256) -> h[k], k in [256,512) -> x0[k-256]
// g_wc[(k*NH+u)*4+g] = (k<256) ? w_hh[(g*256+u)*256 + k] : w_ih[(g*256+u)*256 + (k-256)]
__global__ void pack_weights(const float* __restrict__ w_ih,
                             const float* __restrict__ w_hh) {
    int idx = blockIdx.x * blockDim.x + threadIdx.x;   // 0 .. 512*1024-1
    int k = idx >> 10;            // 0..511
    int j = idx & 1023;           // gate-major row of weight matrix
    int g = j >> 8;
    int u = j & 255;
    float v = (k < NH) ? w_hh[j * NH + k] : w_ih[j * NH + (k - NH)];
    g_wc[((size_t)k * NH + u) * 4 + g] = v;
}

// ---------------- kernel 1: x0 = relu(x @ w_in^T + b_in) ----------------
__global__ __launch_bounds__(256) void in_proj(const float* __restrict__ x,
                                               const float* __restrict__ w_in,
                                               const float* __restrict__ b_in) {
    __shared__ float ws[NX][NH];   // ws[k][u] = w_in[u][k]
    __shared__ float xs[16][NX];
    int tid = threadIdx.x;
    for (int i = tid; i < NH * NX; i += 256) {
        int u = i >> 4, k = i & 15;
        ws[k][u] = w_in[i];
    }
    size_t row0 = (size_t)blockIdx.x * 16;
    {
        int r = tid >> 4, k = tid & 15;
        xs[r][k] = x[(row0 + r) * NX + k];
    }
    __syncthreads();
    int u = tid;
    float b = b_in[u];
#pragma unroll 4
    for (int r = 0; r < 16; r++) {
        float s = b;
#pragma unroll
        for (int k = 0; k < NX; k++) s = fmaf(xs[r][k], ws[k][u], s);
        g_x0[(row0 + r) * NH + u] = fmaxf(s, 0.0f);
    }
}

// ---------------- kernel 2: persistent fused LSTM scan ----------------
// 128 CTAs x 256 threads. CTA owns 16 batch rows for all 365 steps.
// act_s[m][0:256] = h(t-1), act_s[m][256:512] = x0(t). Thread u owns hidden
// unit u (all 4 gates, all 16 rows); c stays in registers. k-loop runs 512.
__global__ __launch_bounds__(256, 1) void lstm_scan(const float* __restrict__ b_ih,
                                                    const float* __restrict__ b_hh,
                                                    const float* __restrict__ w_out,
                                                    const float* __restrict__ b_out,
                                                    float* __restrict__ out) {
    __shared__ float act_s[16][K2];
    __shared__ float wout_s[NH];

    const int tid = threadIdx.x;
    const int u = tid;
    const int lane = tid & 31;
    const int wid = tid >> 5;
    const size_t row0 = (size_t)blockIdx.x * 16;

    wout_s[u] = w_out[u];

    // bias per gate for this thread's hidden unit
    float bi = b_ih[0 * NH + u] + b_hh[0 * NH + u];
    float bf = b_ih[1 * NH + u] + b_hh[1 * NH + u];
    float bg = b_ih[2 * NH + u] + b_hh[2 * NH + u];
    float bo = b_ih[3 * NH + u] + b_hh[3 * NH + u];

    // init: h = 0, load x0 for t=0
#pragma unroll
    for (int m = 0; m < 16; m++) {
        act_s[m][u] = 0.0f;
        act_s[m][NH + u] = g_x0[(row0 + m) * NH + u];
    }

    float c_reg[16];
#pragma unroll
    for (int m = 0; m < 16; m++) c_reg[m] = 0.0f;

    const float b_out0 = b_out[0];
    const float4* __restrict__ W4 = reinterpret_cast<const float4*>(g_wc);
    __syncthreads();

    for (int t = 0; t < NT; t++) {
        float ai[16], af[16], ag[16], ao[16];
#pragma unroll
        for (int m = 0; m < 16; m++) { ai[m] = 0.f; af[m] = 0.f; ag[m] = 0.f; ao[m] = 0.f; }

        // [h ; x0] @ Wc^T, k streamed in chunks of 4 with one-chunk-ahead prefetch
        float4 w0 = W4[0 * NH + u];
        float4 w1 = W4[1 * NH + u];
        float4 w2 = W4[2 * NH + u];
        float4 w3 = W4[3 * NH + u];
        for (int kc = 0; kc < K2; kc += 4) {
            float4 n0v = W4[(size_t)(kc + 4) * NH + u];   // pad rows keep this in-bounds
            float4 n1v = W4[(size_t)(kc + 5) * NH + u];
            float4 n2v = W4[(size_t)(kc + 6) * NH + u];
            float4 n3v = W4[(size_t)(kc + 7) * NH + u];
#pragma unroll
            for (int m = 0; m < 16; m++) {
                float4 a = *(const float4*)&act_s[m][kc];
                ai[m] = fmaf(a.x, w0.x, ai[m]); af[m] = fmaf(a.x, w0.y, af[m]);
                ag[m] = fmaf(a.x, w0.z, ag[m]); ao[m] = fmaf(a.x, w0.w, ao[m]);
                ai[m] = fmaf(a.y, w1.x, ai[m]); af[m] = fmaf(a.y, w1.y, af[m]);
                ag[m] = fmaf(a.y, w1.z, ag[m]); ao[m] = fmaf(a.y, w1.w, ao[m]);
                ai[m] = fmaf(a.z, w2.x, ai[m]); af[m] = fmaf(a.z, w2.y, af[m]);
                ag[m] = fmaf(a.z, w2.z, ag[m]); ao[m] = fmaf(a.z, w2.w, ao[m]);
                ai[m] = fmaf(a.w, w3.x, ai[m]); af[m] = fmaf(a.w, w3.y, af[m]);
                ag[m] = fmaf(a.w, w3.z, ag[m]); ao[m] = fmaf(a.w, w3.w, ao[m]);
            }
            w0 = n0v; w1 = n1v; w2 = n2v; w3 = n3v;
        }
        __syncthreads();   // all reads of act_s (step t state) done

        // activations + state update; write h(t), preload x0(t+1)
#pragma unroll
        for (int m = 0; m < 16; m++) {
            float iv = sigf(ai[m] + bi);
            float fv = sigf(af[m] + bf);
            float gv = tanhf(ag[m] + bg);
            float ov = sigf(ao[m] + bo);
            float c  = fmaf(fv, c_reg[m], iv * gv);
            c_reg[m] = c;
            act_s[m][u] = ov * tanhf(c);
            if (t + 1 < NT)
                act_s[m][NH + u] = g_x0[((size_t)(t + 1) * NGRID + row0 + m) * NH + u];
        }
        __syncthreads();   // act_s for step t+1 ready (h part is h(t))

        // output projection for step t: warp w handles rows 2w, 2w+1 (reads h part only)
#pragma unroll
        for (int mm = 0; mm < 2; mm++) {
            int m = wid * 2 + mm;
            float s = 0.0f;
#pragma unroll
            for (int q = 0; q < 8; q++) {
                int uu = lane + q * 32;
                s = fmaf(act_s[m][uu], wout_s[uu], s);
            }
#pragma unroll
            for (int off = 16; off; off >>= 1) s += __shfl_down_sync(0xffffffffu, s, off);
            if (lane == 0) out[(size_t)t * NGRID + row0 + m] = s + b_out0;
        }
        // next k-loop and this reduction both only READ act_s -> no extra sync needed
    }
}

// ---------------- launch ----------------
extern "C" void kernel_launch(void* const* d_in, const int* in_sizes, int n_in,
                              void* d_out, int out_size) {
    const float* x     = (const float*)d_in[0];
    const float* w_in  = (const float*)d_in[1];
    const float* b_in  = (const float*)d_in[2];
    const float* w_ih  = (const float*)d_in[3];
    const float* w_hh  = (const float*)d_in[4];
    const float* b_ih  = (const float*)d_in[5];
    const float* b_hh  = (const float*)d_in[6];
    const float* w_out = (const float*)d_in[7];
    const float* b_out = (const float*)d_in[8];
    float* out = (float*)d_out;

    pack_weights<<<K2 * G4 / 256, 256>>>(w_ih, w_hh);
    in_proj<<<NROWS / 16, 256>>>(x, w_in, b_in);
    lstm_scan<<<NGRID / 16, 256>>>(b_ih, b_hh, w_out, b_out, out);
}